// round 8
// baseline (speedup 1.0000x reference)
#include <cuda_runtime.h>
#include <math.h>
#include <stdint.h>

#define H_DIM 1024
#define SB 104448
#define OUT_CH 904
#define NMIX 50
#define FULLMASK 0xFFFFFFFFu

typedef unsigned long long ull;

__device__ __forceinline__ float fadd_s(float a, float b) { return __fadd_rn(a, b); }

// ---------------- Threefry2x32 (JAX partitionable) ----------------
struct U2 { unsigned a, b; };
__host__ __device__ constexpr unsigned rotl32(unsigned x, int r) {
  return (x << r) | (x >> (32 - r));
}
__host__ __device__ constexpr U2 threefry2x32(unsigned k0, unsigned k1,
                                              unsigned c0, unsigned c1) {
  unsigned ks[3] = {k0, k1, k0 ^ k1 ^ 0x1BD11BDAu};
  unsigned x0 = c0 + k0, x1 = c1 + k1;
  const int rot[2][4] = {{13, 15, 26, 6}, {17, 29, 16, 24}};
#pragma unroll
  for (int g = 0; g < 5; ++g) {
    const int* r = rot[g & 1];
#pragma unroll
    for (int i = 0; i < 4; ++i) { x0 += x1; x1 = rotl32(x1, r[i]); x1 ^= x0; }
    x0 += ks[(g + 1) % 3];
    x1 += ks[(g + 2) % 3] + (unsigned)(g + 1);
  }
  return U2{x0, x1};
}
constexpr unsigned KCMD0 = threefry2x32(0u, 42u, 0u, 0u).a;
constexpr unsigned KCMD1 = threefry2x32(0u, 42u, 0u, 0u).b;
constexpr unsigned KMIX0 = threefry2x32(0u, 42u, 0u, 1u).a;
constexpr unsigned KMIX1 = threefry2x32(0u, 42u, 0u, 1u).b;
constexpr unsigned KG0   = threefry2x32(0u, 42u, 0u, 2u).a;
constexpr unsigned KG1   = threefry2x32(0u, 42u, 0u, 2u).b;

__device__ __forceinline__ float bits_to_f01(unsigned k0, unsigned k1, unsigned idx) {
  U2 o = threefry2x32(k0, k1, 0u, idx);
  return __uint_as_float((((o.a ^ o.b) >> 9) | 0x3f800000u)) - 1.0f;
}
__device__ __forceinline__ float gumbel_at(unsigned k0, unsigned k1, unsigned idx) {
  float u = fmaxf(bits_to_f01(k0, k1, idx), 1.17549435e-38f);
  return -logf(-logf(u));
}
__device__ __forceinline__ float normal_at(unsigned k0, unsigned k1, unsigned idx) {
  const float lo = __int_as_float(0xBF7FFFFF);  // nextafterf(-1,0)
  float u = fmaxf(__fadd_rn(__fmul_rn(bits_to_f01(k0, k1, idx), 2.0f), lo), lo);
  return __fmul_rn(1.41421356237f, erfinvf(u));
}

__device__ float g_ret[(size_t)SB * OUT_CH];

// ---------------- GEMM: kc=320 panel chains, FFMA2 (fma.rn.f32x2) ------------
// Bit-identical per-element math to round 6/7: for each (m,n), ascending-k
// fma.rn.f32 chain within panels [0,320),[320,640),[640,960),[960,1024),
// panel totals folded ascending with rn adds. f32x2 packs two INDEPENDENT
// (m, m+1) chains per instruction -> 2x flops per issue slot.
#define BM 128
#define BN 64
#define BK 16
#define KITERS (H_DIM / BK)  // 64

__global__ void __launch_bounds__(128) gemm_kernel(
    const float* __restrict__ A, const float* __restrict__ W,
    const float* __restrict__ bias) {
  __shared__ float As[2][BK][BM + 4];
  __shared__ float Ws[2][BK][BN + 4];

  const int bn = blockIdx.x * BN;   // fastest axis -> W + A super-row hot in L2
  const int bm = blockIdx.y * BM;
  const int tid = (int)threadIdx.x;
  const int lr = tid >> 2;          // 0..31
  const int lk = (tid & 3) << 2;    // 0,4,8,12
  const int ty = tid >> 3, tx = tid & 7;

  const float* Abase = A + (size_t)bm * H_DIM + lk;
  float4 pa[4];
  float4 pw[2];

#define LOAD_GLOBAL(K0)                                                        \
  {                                                                            \
    _Pragma("unroll") for (int i = 0; i < 4; ++i) pa[i] =                      \
        *reinterpret_cast<const float4*>(Abase + (size_t)(lr + 32 * i) * H_DIM + (K0)); \
    _Pragma("unroll") for (int i = 0; i < 2; ++i) {                            \
      int ng = bn + lr + 32 * i;                                               \
      pw[i] = make_float4(0.f, 0.f, 0.f, 0.f);                                 \
      if (ng < OUT_CH)                                                         \
        pw[i] = *reinterpret_cast<const float4*>(W + (size_t)ng * H_DIM + (K0) + lk); \
    }                                                                          \
  }

#define STORE_SMEM(BUF)                                                        \
  {                                                                            \
    _Pragma("unroll") for (int i = 0; i < 4; ++i) {                            \
      int m = lr + 32 * i;                                                     \
      As[BUF][lk + 0][m] = pa[i].x; As[BUF][lk + 1][m] = pa[i].y;              \
      As[BUF][lk + 2][m] = pa[i].z; As[BUF][lk + 3][m] = pa[i].w;              \
    }                                                                          \
    _Pragma("unroll") for (int i = 0; i < 2; ++i) {                            \
      int n = lr + 32 * i;                                                     \
      Ws[BUF][lk + 0][n] = pw[i].x; Ws[BUF][lk + 1][n] = pw[i].y;              \
      Ws[BUF][lk + 2][n] = pw[i].z; Ws[BUF][lk + 3][n] = pw[i].w;              \
    }                                                                          \
  }

  // acc2[i2][j]: packed pair (m = ty*8+2*i2 -> low lane, m+1 -> high lane)
  ull acc2[4][8], tot2[4][8];
#pragma unroll
  for (int i = 0; i < 4; ++i)
#pragma unroll
    for (int j = 0; j < 8; ++j) { acc2[i][j] = 0ULL; tot2[i][j] = 0ULL; }

  LOAD_GLOBAL(0)
  STORE_SMEM(0)
  __syncthreads();

  for (int it = 0; it < KITERS; ++it) {
    const int cur = it & 1;
    if (it + 1 < KITERS) LOAD_GLOBAL((it + 1) * BK)

#pragma unroll
    for (int kk = 0; kk < BK; ++kk) {
      // a-pairs load directly as 64-bit words (consecutive m, 8B-aligned)
      ull a2[4];
      const ull* ap = reinterpret_cast<const ull*>(&As[cur][kk][ty * 8]);
      a2[0] = ap[0]; a2[1] = ap[1]; a2[2] = ap[2]; a2[3] = ap[3];

      float bf[8];
      *reinterpret_cast<float4*>(&bf[0]) =
          *reinterpret_cast<const float4*>(&Ws[cur][kk][tx * 8]);
      *reinterpret_cast<float4*>(&bf[4]) =
          *reinterpret_cast<const float4*>(&Ws[cur][kk][tx * 8 + 4]);
      ull b2[8];
#pragma unroll
      for (int j = 0; j < 8; ++j)
        asm("mov.b64 %0, {%1, %1};" : "=l"(b2[j]) : "f"(bf[j]));

#pragma unroll
      for (int i2 = 0; i2 < 4; ++i2)
#pragma unroll
        for (int j = 0; j < 8; ++j)
          asm("fma.rn.f32x2 %0, %1, %2, %0;"
              : "+l"(acc2[i2][j]) : "l"(a2[i2]), "l"(b2[j]));
    }

    int ke = (it + 1) * BK;  // kc=320 fold points: 320, 640, 960, 1024
    if ((ke % 320) == 0 || ke == H_DIM) {
#pragma unroll
      for (int i2 = 0; i2 < 4; ++i2)
#pragma unroll
        for (int j = 0; j < 8; ++j) {
          asm("add.rn.f32x2 %0, %0, %1;" : "+l"(tot2[i2][j]) : "l"(acc2[i2][j]));
          acc2[i2][j] = 0ULL;
        }
    }

    if (it + 1 < KITERS) STORE_SMEM((it + 1) & 1)
    __syncthreads();
  }

  // epilogue: unpack pairs, + bias (rn), store
#pragma unroll
  for (int i2 = 0; i2 < 4; ++i2) {
    int m = bm + ty * 8 + 2 * i2;
    float* o0 = g_ret + (size_t)m * OUT_CH;
    float* o1 = o0 + OUT_CH;
#pragma unroll
    for (int j = 0; j < 8; ++j) {
      int n = bn + tx * 8 + j;
      float lo, hi;
      asm("mov.b64 {%0, %1}, %2;" : "=f"(lo), "=f"(hi) : "l"(tot2[i2][j]));
      if (n < OUT_CH) {
        float bv = __ldg(&bias[n]);
        o0[n] = fadd_s(lo, bv);
        o1[n] = fadd_s(hi, bv);
      }
    }
  }
#undef LOAD_GLOBAL
#undef STORE_SMEM
}

// ---------------- Sampling: one warp per (s,b) row (unchanged) ----------------
__global__ void __launch_bounds__(256) sample_kernel(float* __restrict__ out) {
  int gw = (int)((blockIdx.x * blockDim.x + threadIdx.x) >> 5);
  int lane = (int)(threadIdx.x & 31);
  if (gw >= SB) return;
  const float* row = g_ret + (size_t)gw * OUT_CH;

  float v = __int_as_float(0xFF800000);
  int vi = lane;
  if (lane < 4)
    v = __fadd_rn(__fdiv_rn(row[lane], 1e-4f),
                  gumbel_at(KCMD0, KCMD1, (unsigned)(gw * 4 + lane)));
#pragma unroll
  for (int off = 16; off > 0; off >>= 1) {
    float vo = __shfl_xor_sync(FULLMASK, v, off);
    int io = __shfl_xor_sync(FULLMASK, vi, off);
    if (vo > v || (vo == v && io < vi)) { v = vo; vi = io; }
  }
  if (lane < 4) out[(size_t)gw * 10 + lane] = (lane == vi) ? 1.0f : 0.0f;

  for (int j = 0; j < 6; ++j) {
    const float* p = row + 4 + j * 150;
    const int t1 = lane + 32;
    const bool has1 = (t1 < NMIX);
    float x0 = p[lane];
    float x1 = has1 ? p[t1] : __int_as_float(0xFF800000);

    float mx = fmaxf(x0, x1);
#pragma unroll
    for (int off = 16; off > 0; off >>= 1)
      mx = fmaxf(mx, __shfl_xor_sync(FULLMASK, mx, off));
    float s = expf(x0 - mx) + (has1 ? expf(x1 - mx) : 0.0f);
#pragma unroll
    for (int off = 16; off > 0; off >>= 1)
      s += __shfl_xor_sync(FULLMASK, s, off);
    float lse = logf(s) + mx;

    float y0 = __fdiv_rn(__fadd_rn(x0, -lse), 1e-4f);
    float y1 = has1 ? __fdiv_rn(__fadd_rn(x1, -lse), 1e-4f) : __int_as_float(0xFF800000);
    float ym = fmaxf(y0, y1);
#pragma unroll
    for (int off = 16; off > 0; off >>= 1)
      ym = fmaxf(ym, __shfl_xor_sync(FULLMASK, ym, off));

    float thr = ym - 20.45f;  // gumbel spread <= 20.412
    unsigned m0 = __ballot_sync(FULLMASK, y0 >= thr);
    unsigned m1 = __ballot_sync(FULLMASK, has1 && (y1 >= thr));
    int mixidx;
    if (__popc(m0) + __popc(m1) == 1) {
      mixidx = m0 ? (__ffs(m0) - 1) : (__ffs(m1) + 31);
    } else {
      unsigned base = (unsigned)(gw * 6 + j) * 50u;
      float z = __int_as_float(0xFF800000);
      int zi = 64;
      if (y0 >= thr) { z = __fadd_rn(y0, gumbel_at(KMIX0, KMIX1, base + (unsigned)lane)); zi = lane; }
      if (has1 && y1 >= thr) {
        float z1 = __fadd_rn(y1, gumbel_at(KMIX0, KMIX1, base + (unsigned)t1));
        if (z1 > z) { z = z1; zi = t1; }
      }
#pragma unroll
      for (int off = 16; off > 0; off >>= 1) {
        float zo = __shfl_xor_sync(FULLMASK, z, off);
        int io = __shfl_xor_sync(FULLMASK, zi, off);
        if (zo > z || (zo == z && io < zi)) { z = zo; zi = io; }
      }
      mixidx = zi;
    }

    if (lane == 0) {
      float nrm = normal_at(KG0, KG1, (unsigned)(gw * 6 + j));
      float noise = __fmul_rn(nrm, 0.01f);
      out[(size_t)gw * 10 + 4 + j] =
          __fadd_rn(p[50 + mixidx], __fmul_rn(expf(p[100 + mixidx]), noise));
    }
  }
}

extern "C" void kernel_launch(void* const* d_in, const int* in_sizes, int n_in,
                              void* d_out, int out_size) {
  const float* A = (const float*)d_in[0];
  const float* W = (const float*)d_in[1];
  const float* bias = (const float*)d_in[2];
  float* out = (float*)d_out;

  dim3 ggrid((OUT_CH + BN - 1) / BN, SB / BM);  // (15, 816), bn fastest
  gemm_kernel<<<ggrid, 128>>>(A, W, bias);
  sample_kernel<<<SB / 8, 256>>>(out);
}

// round 11
// speedup vs baseline: 1.3254x; 1.3254x over previous
#include <cuda_runtime.h>
#include <cuda_bf16.h>
#include <math.h>
#include <stdint.h>

#define H_DIM 1024
#define SB 104448
#define OUT_CH 904
#define NMIX 50
#define MIXCH 304   // 4 cmd + 6*50 logmix channels (exact FFMA path)
#define MSPAD 640   // 600 mean/logstd channels padded to 640 (HMMA path)
#define FULLMASK 0xFFFFFFFFu
typedef unsigned long long ull;

__device__ __forceinline__ float fadd_s(float a, float b) { return __fadd_rn(a, b); }

// packed-column -> original-channel maps
__device__ __forceinline__ int cmap_mix(int n) {   // n in [0,304)
  return (n < 4) ? n : 4 + 150 * ((n - 4) / 50) + (n - 4) % 50;
}
__device__ __forceinline__ int cmap_ms(int n) {    // n in [0,600): mean/logstd
  return 4 + 150 * (n / 100) + 50 + (n % 100);
}

// ---------------- Threefry2x32 (JAX partitionable) ----------------
struct U2 { unsigned a, b; };
__host__ __device__ constexpr unsigned rotl32(unsigned x, int r) {
  return (x << r) | (x >> (32 - r));
}
__host__ __device__ constexpr U2 threefry2x32(unsigned k0, unsigned k1,
                                              unsigned c0, unsigned c1) {
  unsigned ks[3] = {k0, k1, k0 ^ k1 ^ 0x1BD11BDAu};
  unsigned x0 = c0 + k0, x1 = c1 + k1;
  const int rot[2][4] = {{13, 15, 26, 6}, {17, 29, 16, 24}};
#pragma unroll
  for (int g = 0; g < 5; ++g) {
    const int* r = rot[g & 1];
#pragma unroll
    for (int i = 0; i < 4; ++i) { x0 += x1; x1 = rotl32(x1, r[i]); x1 ^= x0; }
    x0 += ks[(g + 1) % 3];
    x1 += ks[(g + 2) % 3] + (unsigned)(g + 1);
  }
  return U2{x0, x1};
}
constexpr unsigned KCMD0 = threefry2x32(0u, 42u, 0u, 0u).a;
constexpr unsigned KCMD1 = threefry2x32(0u, 42u, 0u, 0u).b;
constexpr unsigned KMIX0 = threefry2x32(0u, 42u, 0u, 1u).a;
constexpr unsigned KMIX1 = threefry2x32(0u, 42u, 0u, 1u).b;
constexpr unsigned KG0   = threefry2x32(0u, 42u, 0u, 2u).a;
constexpr unsigned KG1   = threefry2x32(0u, 42u, 0u, 2u).b;

__device__ __forceinline__ float bits_to_f01(unsigned k0, unsigned k1, unsigned idx) {
  U2 o = threefry2x32(k0, k1, 0u, idx);
  return __uint_as_float((((o.a ^ o.b) >> 9) | 0x3f800000u)) - 1.0f;
}
__device__ __forceinline__ float gumbel_at(unsigned k0, unsigned k1, unsigned idx) {
  float u = fmaxf(bits_to_f01(k0, k1, idx), 1.17549435e-38f);
  return -logf(-logf(u));
}
__device__ __forceinline__ float normal_at(unsigned k0, unsigned k1, unsigned idx) {
  const float lo = __int_as_float(0xBF7FFFFF);  // nextafterf(-1,0)
  float u = fmaxf(__fadd_rn(__fmul_rn(bits_to_f01(k0, k1, idx), 2.0f), lo), lo);
  return __fmul_rn(1.41421356237f, erfinvf(u));
}

// ---------------- Device scratch ----------------
__device__ float g_mix[(size_t)SB * MIXCH];          // exact logits (bias added)
__device__ float g_ms[(size_t)SB * MSPAD];           // mean/logstd (NO bias)
__device__ __nv_bfloat16 g_ah[(size_t)SB * H_DIM];   // A hi
__device__ __nv_bfloat16 g_al[(size_t)SB * H_DIM];   // A lo
__device__ __nv_bfloat16 g_wh[(size_t)MSPAD * H_DIM];
__device__ __nv_bfloat16 g_wl[(size_t)MSPAD * H_DIM];

// ---------------- Splitters ----------------
__global__ void __launch_bounds__(256) split_a_kernel(const float* __restrict__ A) {
  size_t i = (size_t)blockIdx.x * 256 + threadIdx.x;  // one float4 per thread
  float4 v = reinterpret_cast<const float4*>(A)[i];
  float f[4] = {v.x, v.y, v.z, v.w};
  ull hp = 0, lp = 0;
#pragma unroll
  for (int j = 0; j < 4; ++j) {
    __nv_bfloat16 h = __float2bfloat16(f[j]);
    __nv_bfloat16 l = __float2bfloat16(__fadd_rn(f[j], -__bfloat162float(h)));
    hp |= (ull)__bfloat16_as_ushort(h) << (16 * j);
    lp |= (ull)__bfloat16_as_ushort(l) << (16 * j);
  }
  reinterpret_cast<ull*>(g_ah)[i] = hp;
  reinterpret_cast<ull*>(g_al)[i] = lp;
}

__global__ void __launch_bounds__(256) split_w_kernel(const float* __restrict__ W) {
  size_t i = (size_t)blockIdx.x * 256 + threadIdx.x;  // one float4-slot per thread
  int n = (int)(i / (H_DIM / 4));
  int k4 = (int)(i % (H_DIM / 4));
  ull hp = 0, lp = 0;
  if (n < 600) {
    int c = cmap_ms(n);
    float4 v = reinterpret_cast<const float4*>(W + (size_t)c * H_DIM)[k4];
    float f[4] = {v.x, v.y, v.z, v.w};
#pragma unroll
    for (int j = 0; j < 4; ++j) {
      __nv_bfloat16 h = __float2bfloat16(f[j]);
      __nv_bfloat16 l = __float2bfloat16(__fadd_rn(f[j], -__bfloat162float(h)));
      hp |= (ull)__bfloat16_as_ushort(h) << (16 * j);
      lp |= (ull)__bfloat16_as_ushort(l) << (16 * j);
    }
  }
  reinterpret_cast<ull*>(g_wh)[i] = hp;
  reinterpret_cast<ull*>(g_wl)[i] = lp;
}

// ---------------- FFMA GEMM: 304 exact channels, kc=320 chains (LOCKED) ------
#define BM 128
#define BN 64
#define BK 16
#define KITERS (H_DIM / BK)  // 64

__global__ void __launch_bounds__(128) gemm_mix_kernel(
    const float* __restrict__ A, const float* __restrict__ W,
    const float* __restrict__ bias) {
  __shared__ float As[2][BK][BM + 4];
  __shared__ float Ws[2][BK][BN + 4];

  const int bn = blockIdx.x * BN;   // 5 blocks (320 cols, mask at 304)
  const int bm = blockIdx.y * BM;
  const int tid = (int)threadIdx.x;
  const int lr = tid >> 2;
  const int lk = (tid & 3) << 2;
  const int ty = tid >> 3, tx = tid & 7;

  const float* Abase = A + (size_t)bm * H_DIM + lk;
  const int n0 = bn + lr, n1 = bn + lr + 32;
  const bool wv0 = n0 < MIXCH, wv1 = n1 < MIXCH;
  const float* wr0 = W + (size_t)cmap_mix(wv0 ? n0 : 0) * H_DIM + lk;
  const float* wr1 = W + (size_t)cmap_mix(wv1 ? n1 : 0) * H_DIM + lk;

  float4 pa[4];
  float4 pw[2];

#define LOAD_GLOBAL(K0)                                                        \
  {                                                                            \
    _Pragma("unroll") for (int i = 0; i < 4; ++i) pa[i] =                      \
        *reinterpret_cast<const float4*>(Abase + (size_t)(lr + 32 * i) * H_DIM + (K0)); \
    pw[0] = wv0 ? *reinterpret_cast<const float4*>(wr0 + (K0))                 \
                : make_float4(0.f, 0.f, 0.f, 0.f);                             \
    pw[1] = wv1 ? *reinterpret_cast<const float4*>(wr1 + (K0))                 \
                : make_float4(0.f, 0.f, 0.f, 0.f);                             \
  }

#define STORE_SMEM(BUF)                                                        \
  {                                                                            \
    _Pragma("unroll") for (int i = 0; i < 4; ++i) {                            \
      int m = lr + 32 * i;                                                     \
      As[BUF][lk + 0][m] = pa[i].x; As[BUF][lk + 1][m] = pa[i].y;              \
      As[BUF][lk + 2][m] = pa[i].z; As[BUF][lk + 3][m] = pa[i].w;              \
    }                                                                          \
    _Pragma("unroll") for (int i = 0; i < 2; ++i) {                            \
      int n = lr + 32 * i;                                                     \
      Ws[BUF][lk + 0][n] = pw[i].x; Ws[BUF][lk + 1][n] = pw[i].y;              \
      Ws[BUF][lk + 2][n] = pw[i].z; Ws[BUF][lk + 3][n] = pw[i].w;              \
    }                                                                          \
  }

  float acc[8][8], tot[8][8];
#pragma unroll
  for (int i = 0; i < 8; ++i)
#pragma unroll
    for (int j = 0; j < 8; ++j) { acc[i][j] = 0.0f; tot[i][j] = 0.0f; }

  LOAD_GLOBAL(0)
  STORE_SMEM(0)
  __syncthreads();

  for (int it = 0; it < KITERS; ++it) {
    const int cur = it & 1;
    if (it + 1 < KITERS) LOAD_GLOBAL((it + 1) * BK)

#pragma unroll
    for (int kk = 0; kk < BK; ++kk) {
      float af[8], bf[8];
      *reinterpret_cast<float4*>(&af[0]) = *reinterpret_cast<const float4*>(&As[cur][kk][ty * 8]);
      *reinterpret_cast<float4*>(&af[4]) = *reinterpret_cast<const float4*>(&As[cur][kk][ty * 8 + 4]);
      *reinterpret_cast<float4*>(&bf[0]) = *reinterpret_cast<const float4*>(&Ws[cur][kk][tx * 8]);
      *reinterpret_cast<float4*>(&bf[4]) = *reinterpret_cast<const float4*>(&Ws[cur][kk][tx * 8 + 4]);
#pragma unroll
      for (int i = 0; i < 8; ++i)
#pragma unroll
        for (int j = 0; j < 8; ++j) acc[i][j] = fmaf(af[i], bf[j], acc[i][j]);
    }

    int ke = (it + 1) * BK;  // kc=320 fold points: 320, 640, 960, 1024
    if ((ke % 320) == 0 || ke == H_DIM) {
#pragma unroll
      for (int i = 0; i < 8; ++i)
#pragma unroll
        for (int j = 0; j < 8; ++j) { tot[i][j] = fadd_s(tot[i][j], acc[i][j]); acc[i][j] = 0.0f; }
    }

    if (it + 1 < KITERS) STORE_SMEM((it + 1) & 1)
    __syncthreads();
  }

#pragma unroll
  for (int i = 0; i < 8; ++i) {
    float* o = g_mix + (size_t)(bm + ty * 8 + i) * MIXCH;
#pragma unroll
    for (int j = 0; j < 8; ++j) {
      int n = bn + tx * 8 + j;
      if (n < MIXCH) o[n] = fadd_s(tot[i][j], __ldg(&bias[cmap_mix(n)]));
    }
  }
#undef LOAD_GLOBAL
#undef STORE_SMEM
}

// ---------------- HMMA GEMM (mma.sync bf16): 600 mean/logstd channels --------
// D = Ah*Wh + Ah*Wl + Al*Wh. Block 128x64, 8 warps (4m x 2n), warp tile 32x32.
#define MS_STRIDE 72  // bf16 elems per smem row (64 + 8 pad)

__device__ __forceinline__ void mma_bf16(float c[4], uint32_t a0, uint32_t a1,
                                         uint32_t a2, uint32_t a3,
                                         uint32_t b0, uint32_t b1) {
  asm volatile(
      "mma.sync.aligned.m16n8k16.row.col.f32.bf16.bf16.f32 "
      "{%0,%1,%2,%3}, {%4,%5,%6,%7}, {%8,%9}, {%0,%1,%2,%3};"
      : "+f"(c[0]), "+f"(c[1]), "+f"(c[2]), "+f"(c[3])
      : "r"(a0), "r"(a1), "r"(a2), "r"(a3), "r"(b0), "r"(b1));
}

__global__ void __launch_bounds__(256) gemm_ms_kernel() {
  extern __shared__ __nv_bfloat16 sm[];
  __nv_bfloat16* sAh = sm;
  __nv_bfloat16* sAl = sAh + 128 * MS_STRIDE;
  __nv_bfloat16* sWh = sAl + 128 * MS_STRIDE;
  __nv_bfloat16* sWl = sWh + 64 * MS_STRIDE;

  const int bn = blockIdx.x * 64;   // 10 (fastest -> A hot in L2)
  const int bm = blockIdx.y * 128;  // 816
  const int tid = (int)threadIdx.x;
  const int wid = tid >> 5, lane = tid & 31;
  const int wm = (wid >> 1) * 32, wn = (wid & 1) * 32;
  const int g = lane >> 2, q = lane & 3;  // fragment group / quad

  float c[2][4][4];
#pragma unroll
  for (int mt = 0; mt < 2; ++mt)
#pragma unroll
    for (int nt = 0; nt < 4; ++nt)
#pragma unroll
      for (int r = 0; r < 4; ++r) c[mt][nt][r] = 0.0f;

  for (int ch = 0; ch < H_DIM / 64; ++ch) {
    const int k0 = ch * 64;
    {  // A tiles: 2 threads/row, 32 bf16 = 64 B = 4 x uint4 each  (BUG FIXED)
      int r = tid >> 1, h = (tid & 1) * 32;
      const uint4* srch = reinterpret_cast<const uint4*>(g_ah + (size_t)(bm + r) * H_DIM + k0 + h);
      const uint4* srcl = reinterpret_cast<const uint4*>(g_al + (size_t)(bm + r) * H_DIM + k0 + h);
      uint4* dh = reinterpret_cast<uint4*>(sAh + r * MS_STRIDE + h);
      uint4* dl = reinterpret_cast<uint4*>(sAl + r * MS_STRIDE + h);
#pragma unroll
      for (int i = 0; i < 4; ++i) { dh[i] = srch[i]; dl[i] = srcl[i]; }
    }
    if (tid < 128) {  // W tiles: 64 rows, same 64 B per thread
      int r = tid >> 1, h = (tid & 1) * 32;
      const uint4* srch = reinterpret_cast<const uint4*>(g_wh + (size_t)(bn + r) * H_DIM + k0 + h);
      const uint4* srcl = reinterpret_cast<const uint4*>(g_wl + (size_t)(bn + r) * H_DIM + k0 + h);
      uint4* dh = reinterpret_cast<uint4*>(sWh + r * MS_STRIDE + h);
      uint4* dl = reinterpret_cast<uint4*>(sWl + r * MS_STRIDE + h);
#pragma unroll
      for (int i = 0; i < 4; ++i) { dh[i] = srch[i]; dl[i] = srcl[i]; }
    }
    __syncthreads();

#pragma unroll
    for (int ks = 0; ks < 4; ++ks) {
      const int kk = ks * 16 + q * 2;
      uint32_t ah[2][4], al[2][4], bh[4][2], bl[4][2];
#pragma unroll
      for (int mt = 0; mt < 2; ++mt) {
        int r0 = wm + mt * 16 + g;
        ah[mt][0] = *reinterpret_cast<const uint32_t*>(sAh + r0 * MS_STRIDE + kk);
        ah[mt][1] = *reinterpret_cast<const uint32_t*>(sAh + (r0 + 8) * MS_STRIDE + kk);
        ah[mt][2] = *reinterpret_cast<const uint32_t*>(sAh + r0 * MS_STRIDE + kk + 8);
        ah[mt][3] = *reinterpret_cast<const uint32_t*>(sAh + (r0 + 8) * MS_STRIDE + kk + 8);
        al[mt][0] = *reinterpret_cast<const uint32_t*>(sAl + r0 * MS_STRIDE + kk);
        al[mt][1] = *reinterpret_cast<const uint32_t*>(sAl + (r0 + 8) * MS_STRIDE + kk);
        al[mt][2] = *reinterpret_cast<const uint32_t*>(sAl + r0 * MS_STRIDE + kk + 8);
        al[mt][3] = *reinterpret_cast<const uint32_t*>(sAl + (r0 + 8) * MS_STRIDE + kk + 8);
      }
#pragma unroll
      for (int nt = 0; nt < 4; ++nt) {
        int n = wn + nt * 8 + g;
        bh[nt][0] = *reinterpret_cast<const uint32_t*>(sWh + n * MS_STRIDE + kk);
        bh[nt][1] = *reinterpret_cast<const uint32_t*>(sWh + n * MS_STRIDE + kk + 8);
        bl[nt][0] = *reinterpret_cast<const uint32_t*>(sWl + n * MS_STRIDE + kk);
        bl[nt][1] = *reinterpret_cast<const uint32_t*>(sWl + n * MS_STRIDE + kk + 8);
      }
#pragma unroll
      for (int mt = 0; mt < 2; ++mt)
#pragma unroll
        for (int nt = 0; nt < 4; ++nt) {
          mma_bf16(c[mt][nt], ah[mt][0], ah[mt][1], ah[mt][2], ah[mt][3],
                   bh[nt][0], bh[nt][1]);
          mma_bf16(c[mt][nt], ah[mt][0], ah[mt][1], ah[mt][2], ah[mt][3],
                   bl[nt][0], bl[nt][1]);
          mma_bf16(c[mt][nt], al[mt][0], al[mt][1], al[mt][2], al[mt][3],
                   bh[nt][0], bh[nt][1]);
        }
    }
    __syncthreads();
  }

#pragma unroll
  for (int mt = 0; mt < 2; ++mt) {
#pragma unroll
    for (int nt = 0; nt < 4; ++nt) {
      int row = bm + wm + mt * 16 + g;
      int col = bn + wn + nt * 8 + q * 2;
      float2* p0 = reinterpret_cast<float2*>(g_ms + (size_t)row * MSPAD + col);
      float2* p1 = reinterpret_cast<float2*>(g_ms + (size_t)(row + 8) * MSPAD + col);
      *p0 = make_float2(c[mt][nt][0], c[mt][nt][1]);
      *p1 = make_float2(c[mt][nt][2], c[mt][nt][3]);
    }
  }
}

// ---------------- Sampling: one warp per (s,b) row ----------------
__global__ void __launch_bounds__(256) sample_kernel(const float* __restrict__ bias,
                                                     float* __restrict__ out) {
  int gw = (int)((blockIdx.x * blockDim.x + threadIdx.x) >> 5);
  int lane = (int)(threadIdx.x & 31);
  if (gw >= SB) return;
  const float* rmix = g_mix + (size_t)gw * MIXCH;

  float v = __int_as_float(0xFF800000);
  int vi = lane;
  if (lane < 4)
    v = __fadd_rn(__fdiv_rn(rmix[lane], 1e-4f),
                  gumbel_at(KCMD0, KCMD1, (unsigned)(gw * 4 + lane)));
#pragma unroll
  for (int off = 16; off > 0; off >>= 1) {
    float vo = __shfl_xor_sync(FULLMASK, v, off);
    int io = __shfl_xor_sync(FULLMASK, vi, off);
    if (vo > v || (vo == v && io < vi)) { v = vo; vi = io; }
  }
  if (lane < 4) out[(size_t)gw * 10 + lane] = (lane == vi) ? 1.0f : 0.0f;

  for (int j = 0; j < 6; ++j) {
    const float* p = rmix + 4 + j * 50;
    const int t1 = lane + 32;
    const bool has1 = (t1 < NMIX);
    float x0 = p[lane];
    float x1 = has1 ? p[t1] : __int_as_float(0xFF800000);

    float mx = fmaxf(x0, x1);
#pragma unroll
    for (int off = 16; off > 0; off >>= 1)
      mx = fmaxf(mx, __shfl_xor_sync(FULLMASK, mx, off));
    float s = expf(x0 - mx) + (has1 ? expf(x1 - mx) : 0.0f);
#pragma unroll
    for (int off = 16; off > 0; off >>= 1)
      s += __shfl_xor_sync(FULLMASK, s, off);
    float lse = logf(s) + mx;

    float y0 = __fdiv_rn(__fadd_rn(x0, -lse), 1e-4f);
    float y1 = has1 ? __fdiv_rn(__fadd_rn(x1, -lse), 1e-4f) : __int_as_float(0xFF800000);
    float ym = fmaxf(y0, y1);
#pragma unroll
    for (int off = 16; off > 0; off >>= 1)
      ym = fmaxf(ym, __shfl_xor_sync(FULLMASK, ym, off));

    float thr = ym - 20.45f;  // gumbel spread <= 20.412
    unsigned m0 = __ballot_sync(FULLMASK, y0 >= thr);
    unsigned m1 = __ballot_sync(FULLMASK, has1 && (y1 >= thr));
    int mixidx;
    if (__popc(m0) + __popc(m1) == 1) {
      mixidx = m0 ? (__ffs(m0) - 1) : (__ffs(m1) + 31);
    } else {
      unsigned base = (unsigned)(gw * 6 + j) * 50u;
      float z = __int_as_float(0xFF800000);
      int zi = 64;
      if (y0 >= thr) { z = __fadd_rn(y0, gumbel_at(KMIX0, KMIX1, base + (unsigned)lane)); zi = lane; }
      if (has1 && y1 >= thr) {
        float z1 = __fadd_rn(y1, gumbel_at(KMIX0, KMIX1, base + (unsigned)t1));
        if (z1 > z) { z = z1; zi = t1; }
      }
#pragma unroll
      for (int off = 16; off > 0; off >>= 1) {
        float zo = __shfl_xor_sync(FULLMASK, z, off);
        int io = __shfl_xor_sync(FULLMASK, zi, off);
        if (zo > z || (zo == z && io < zi)) { z = zo; zi = io; }
      }
      mixidx = zi;
    }

    if (lane == 0) {
      const float* rms = g_ms + (size_t)gw * MSPAD + j * 100;
      float mean = __fadd_rn(rms[mixidx], __ldg(&bias[4 + 150 * j + 50 + mixidx]));
      float lstd = __fadd_rn(rms[50 + mixidx], __ldg(&bias[4 + 150 * j + 100 + mixidx]));
      float nrm = normal_at(KG0, KG1, (unsigned)(gw * 6 + j));
      float noise = __fmul_rn(nrm, 0.01f);
      out[(size_t)gw * 10 + 4 + j] = __fadd_rn(mean, __fmul_rn(expf(lstd), noise));
    }
  }
}

// ---------------- Launch ----------------
extern "C" void kernel_launch(void* const* d_in, const int* in_sizes, int n_in,
                              void* d_out, int out_size) {
  const float* A = (const float*)d_in[0];
  const float* W = (const float*)d_in[1];
  const float* bias = (const float*)d_in[2];
  float* out = (float*)d_out;

  const int ms_smem = (128 + 128 + 64 + 64) * MS_STRIDE * 2;  // 55296 B
  cudaFuncSetAttribute(gemm_ms_kernel,
                       cudaFuncAttributeMaxDynamicSharedMemorySize, ms_smem);

  split_a_kernel<<<(int)((size_t)SB * H_DIM / 4 / 256), 256>>>(A);
  split_w_kernel<<<(int)((size_t)MSPAD * H_DIM / 4 / 256), 256>>>(W);

  dim3 gmix(MIXCH / BN + (MIXCH % BN != 0), SB / BM);  // (5, 816)
  gemm_mix_kernel<<<gmix, 128>>>(A, W, bias);

  dim3 gms(MSPAD / 64, SB / 128);  // (10, 816)
  gemm_ms_kernel<<<gms, 256, ms_smem>>>();

  sample_kernel<<<SB / 8, 256>>>(bias, out);
}

// round 12
// speedup vs baseline: 1.4376x; 1.0846x over previous
#include <cuda_runtime.h>
#include <cuda_bf16.h>
#include <math.h>
#include <stdint.h>

#define H_DIM 1024
#define SB 104448
#define OUT_CH 904
#define NMIX 50
#define MIXCH 304   // 4 cmd + 6*50 logmix channels (exact FFMA path)
#define MSPAD 640   // 600 mean/logstd channels padded to 640 (HMMA path)
#define FULLMASK 0xFFFFFFFFu
typedef unsigned long long ull;

__device__ __forceinline__ float fadd_s(float a, float b) { return __fadd_rn(a, b); }

// packed-column -> original-channel maps
__device__ __forceinline__ int cmap_mix(int n) {   // n in [0,304)
  return (n < 4) ? n : 4 + 150 * ((n - 4) / 50) + (n - 4) % 50;
}
__device__ __forceinline__ int cmap_ms(int n) {    // n in [0,600): mean/logstd
  return 4 + 150 * (n / 100) + 50 + (n % 100);
}

// ---------------- Threefry2x32 (JAX partitionable) ----------------
struct U2 { unsigned a, b; };
__host__ __device__ constexpr unsigned rotl32(unsigned x, int r) {
  return (x << r) | (x >> (32 - r));
}
__host__ __device__ constexpr U2 threefry2x32(unsigned k0, unsigned k1,
                                              unsigned c0, unsigned c1) {
  unsigned ks[3] = {k0, k1, k0 ^ k1 ^ 0x1BD11BDAu};
  unsigned x0 = c0 + k0, x1 = c1 + k1;
  const int rot[2][4] = {{13, 15, 26, 6}, {17, 29, 16, 24}};
#pragma unroll
  for (int g = 0; g < 5; ++g) {
    const int* r = rot[g & 1];
#pragma unroll
    for (int i = 0; i < 4; ++i) { x0 += x1; x1 = rotl32(x1, r[i]); x1 ^= x0; }
    x0 += ks[(g + 1) % 3];
    x1 += ks[(g + 2) % 3] + (unsigned)(g + 1);
  }
  return U2{x0, x1};
}
constexpr unsigned KCMD0 = threefry2x32(0u, 42u, 0u, 0u).a;
constexpr unsigned KCMD1 = threefry2x32(0u, 42u, 0u, 0u).b;
constexpr unsigned KMIX0 = threefry2x32(0u, 42u, 0u, 1u).a;
constexpr unsigned KMIX1 = threefry2x32(0u, 42u, 0u, 1u).b;
constexpr unsigned KG0   = threefry2x32(0u, 42u, 0u, 2u).a;
constexpr unsigned KG1   = threefry2x32(0u, 42u, 0u, 2u).b;

__device__ __forceinline__ float bits_to_f01(unsigned k0, unsigned k1, unsigned idx) {
  U2 o = threefry2x32(k0, k1, 0u, idx);
  return __uint_as_float((((o.a ^ o.b) >> 9) | 0x3f800000u)) - 1.0f;
}
__device__ __forceinline__ float gumbel_at(unsigned k0, unsigned k1, unsigned idx) {
  float u = fmaxf(bits_to_f01(k0, k1, idx), 1.17549435e-38f);
  return -logf(-logf(u));
}
__device__ __forceinline__ float normal_at(unsigned k0, unsigned k1, unsigned idx) {
  const float lo = __int_as_float(0xBF7FFFFF);  // nextafterf(-1,0)
  float u = fmaxf(__fadd_rn(__fmul_rn(bits_to_f01(k0, k1, idx), 2.0f), lo), lo);
  return __fmul_rn(1.41421356237f, erfinvf(u));
}

// ---------------- Device scratch ----------------
__device__ float g_mix[(size_t)SB * MIXCH];          // exact logits (bias added)
__device__ float g_ms[(size_t)SB * MSPAD];           // mean/logstd (NO bias)
__device__ __nv_bfloat16 g_ah[(size_t)SB * H_DIM];   // A hi
__device__ __nv_bfloat16 g_al[(size_t)SB * H_DIM];   // A lo
__device__ __nv_bfloat16 g_wh[(size_t)MSPAD * H_DIM];
__device__ __nv_bfloat16 g_wl[(size_t)MSPAD * H_DIM];

// ---------------- Splitters ----------------
__global__ void __launch_bounds__(256) split_a_kernel(const float* __restrict__ A) {
  size_t i = (size_t)blockIdx.x * 256 + threadIdx.x;  // one float4 per thread
  float4 v = reinterpret_cast<const float4*>(A)[i];
  float f[4] = {v.x, v.y, v.z, v.w};
  ull hp = 0, lp = 0;
#pragma unroll
  for (int j = 0; j < 4; ++j) {
    __nv_bfloat16 h = __float2bfloat16(f[j]);
    __nv_bfloat16 l = __float2bfloat16(__fadd_rn(f[j], -__bfloat162float(h)));
    hp |= (ull)__bfloat16_as_ushort(h) << (16 * j);
    lp |= (ull)__bfloat16_as_ushort(l) << (16 * j);
  }
  reinterpret_cast<ull*>(g_ah)[i] = hp;
  reinterpret_cast<ull*>(g_al)[i] = lp;
}

__global__ void __launch_bounds__(256) split_w_kernel(const float* __restrict__ W) {
  size_t i = (size_t)blockIdx.x * 256 + threadIdx.x;  // one float4-slot per thread
  int n = (int)(i / (H_DIM / 4));
  int k4 = (int)(i % (H_DIM / 4));
  ull hp = 0, lp = 0;
  if (n < 600) {
    int c = cmap_ms(n);
    float4 v = reinterpret_cast<const float4*>(W + (size_t)c * H_DIM)[k4];
    float f[4] = {v.x, v.y, v.z, v.w};
#pragma unroll
    for (int j = 0; j < 4; ++j) {
      __nv_bfloat16 h = __float2bfloat16(f[j]);
      __nv_bfloat16 l = __float2bfloat16(__fadd_rn(f[j], -__bfloat162float(h)));
      hp |= (ull)__bfloat16_as_ushort(h) << (16 * j);
      lp |= (ull)__bfloat16_as_ushort(l) << (16 * j);
    }
  }
  reinterpret_cast<ull*>(g_wh)[i] = hp;
  reinterpret_cast<ull*>(g_wl)[i] = lp;
}

// ---------------- FFMA GEMM: 304 exact channels, kc=320 chains (LOCKED) ------
#define BM 128
#define BN 64
#define BK 16
#define KITERS (H_DIM / BK)  // 64

__global__ void __launch_bounds__(128) gemm_mix_kernel(
    const float* __restrict__ A, const float* __restrict__ W,
    const float* __restrict__ bias) {
  __shared__ float As[2][BK][BM + 4];
  __shared__ float Ws[2][BK][BN + 4];

  const int bn = blockIdx.x * BN;   // 5 blocks (320 cols, mask at 304)
  const int bm = blockIdx.y * BM;
  const int tid = (int)threadIdx.x;
  const int lr = tid >> 2;
  const int lk = (tid & 3) << 2;
  const int ty = tid >> 3, tx = tid & 7;

  const float* Abase = A + (size_t)bm * H_DIM + lk;
  const int n0 = bn + lr, n1 = bn + lr + 32;
  const bool wv0 = n0 < MIXCH, wv1 = n1 < MIXCH;
  const float* wr0 = W + (size_t)cmap_mix(wv0 ? n0 : 0) * H_DIM + lk;
  const float* wr1 = W + (size_t)cmap_mix(wv1 ? n1 : 0) * H_DIM + lk;

  float4 pa[4];
  float4 pw[2];

#define LOAD_GLOBAL(K0)                                                        \
  {                                                                            \
    _Pragma("unroll") for (int i = 0; i < 4; ++i) pa[i] =                      \
        *reinterpret_cast<const float4*>(Abase + (size_t)(lr + 32 * i) * H_DIM + (K0)); \
    pw[0] = wv0 ? *reinterpret_cast<const float4*>(wr0 + (K0))                 \
                : make_float4(0.f, 0.f, 0.f, 0.f);                             \
    pw[1] = wv1 ? *reinterpret_cast<const float4*>(wr1 + (K0))                 \
                : make_float4(0.f, 0.f, 0.f, 0.f);                             \
  }

#define STORE_SMEM(BUF)                                                        \
  {                                                                            \
    _Pragma("unroll") for (int i = 0; i < 4; ++i) {                            \
      int m = lr + 32 * i;                                                     \
      As[BUF][lk + 0][m] = pa[i].x; As[BUF][lk + 1][m] = pa[i].y;              \
      As[BUF][lk + 2][m] = pa[i].z; As[BUF][lk + 3][m] = pa[i].w;              \
    }                                                                          \
    _Pragma("unroll") for (int i = 0; i < 2; ++i) {                            \
      int n = lr + 32 * i;                                                     \
      Ws[BUF][lk + 0][n] = pw[i].x; Ws[BUF][lk + 1][n] = pw[i].y;              \
      Ws[BUF][lk + 2][n] = pw[i].z; Ws[BUF][lk + 3][n] = pw[i].w;              \
    }                                                                          \
  }

  float acc[8][8], tot[8][8];
#pragma unroll
  for (int i = 0; i < 8; ++i)
#pragma unroll
    for (int j = 0; j < 8; ++j) { acc[i][j] = 0.0f; tot[i][j] = 0.0f; }

  LOAD_GLOBAL(0)
  STORE_SMEM(0)
  __syncthreads();

  for (int it = 0; it < KITERS; ++it) {
    const int cur = it & 1;
    if (it + 1 < KITERS) LOAD_GLOBAL((it + 1) * BK)

#pragma unroll
    for (int kk = 0; kk < BK; ++kk) {
      float af[8], bf[8];
      *reinterpret_cast<float4*>(&af[0]) = *reinterpret_cast<const float4*>(&As[cur][kk][ty * 8]);
      *reinterpret_cast<float4*>(&af[4]) = *reinterpret_cast<const float4*>(&As[cur][kk][ty * 8 + 4]);
      *reinterpret_cast<float4*>(&bf[0]) = *reinterpret_cast<const float4*>(&Ws[cur][kk][tx * 8]);
      *reinterpret_cast<float4*>(&bf[4]) = *reinterpret_cast<const float4*>(&Ws[cur][kk][tx * 8 + 4]);
#pragma unroll
      for (int i = 0; i < 8; ++i)
#pragma unroll
        for (int j = 0; j < 8; ++j) acc[i][j] = fmaf(af[i], bf[j], acc[i][j]);
    }

    int ke = (it + 1) * BK;  // kc=320 fold points: 320, 640, 960, 1024
    if ((ke % 320) == 0 || ke == H_DIM) {
#pragma unroll
      for (int i = 0; i < 8; ++i)
#pragma unroll
        for (int j = 0; j < 8; ++j) { tot[i][j] = fadd_s(tot[i][j], acc[i][j]); acc[i][j] = 0.0f; }
    }

    if (it + 1 < KITERS) STORE_SMEM((it + 1) & 1)
    __syncthreads();
  }

#pragma unroll
  for (int i = 0; i < 8; ++i) {
    float* o = g_mix + (size_t)(bm + ty * 8 + i) * MIXCH;
#pragma unroll
    for (int j = 0; j < 8; ++j) {
      int n = bn + tx * 8 + j;
      if (n < MIXCH) o[n] = fadd_s(tot[i][j], __ldg(&bias[cmap_mix(n)]));
    }
  }
#undef LOAD_GLOBAL
#undef STORE_SMEM
}

// ---------------- HMMA GEMM (mma.sync bf16 + ldmatrix): 600 ms channels ------
// D = Ah*Wh + Ah*Wl + Al*Wh. Block 128x64, 8 warps (4m x 2n), warp tile 32x32.
#define MS_STRIDE 72  // bf16 elems per smem row (64 + 8 pad); 144B = 9*16B -> conflict-free

__device__ __forceinline__ void mma_bf16(float c[4], uint32_t a0, uint32_t a1,
                                         uint32_t a2, uint32_t a3,
                                         uint32_t b0, uint32_t b1) {
  asm volatile(
      "mma.sync.aligned.m16n8k16.row.col.f32.bf16.bf16.f32 "
      "{%0,%1,%2,%3}, {%4,%5,%6,%7}, {%8,%9}, {%0,%1,%2,%3};"
      : "+f"(c[0]), "+f"(c[1]), "+f"(c[2]), "+f"(c[3])
      : "r"(a0), "r"(a1), "r"(a2), "r"(a3), "r"(b0), "r"(b1));
}

#define LDMX4(R0, R1, R2, R3, ADDR)                                            \
  asm volatile("ldmatrix.sync.aligned.m8n8.x4.shared.b16 {%0,%1,%2,%3}, [%4];" \
               : "=r"(R0), "=r"(R1), "=r"(R2), "=r"(R3) : "r"(ADDR))

__device__ __forceinline__ uint32_t smem_u32(const void* p) {
  uint32_t a;
  asm("{ .reg .u64 t; cvta.to.shared.u64 t, %1; cvt.u32.u64 %0, t; }" : "=r"(a) : "l"(p));
  return a;
}

__global__ void __launch_bounds__(256) gemm_ms_kernel() {
  extern __shared__ __nv_bfloat16 sm[];
  __nv_bfloat16* sAh = sm;
  __nv_bfloat16* sAl = sAh + 128 * MS_STRIDE;
  __nv_bfloat16* sWh = sAl + 128 * MS_STRIDE;
  __nv_bfloat16* sWl = sWh + 64 * MS_STRIDE;

  const int bn = blockIdx.x * 64;   // 10 (fastest -> A hot in L2)
  const int bm = blockIdx.y * 128;  // 816
  const int tid = (int)threadIdx.x;
  const int wid = tid >> 5, lane = tid & 31;
  const int wm = (wid >> 1) * 32, wn = (wid & 1) * 32;
  const int g = lane >> 2, q = lane & 3;  // C-fragment group / quad

  // ldmatrix per-lane row/col selectors
  const int a_row = wm + (lane & 15);                              // + mt*16
  const int a_sel = (lane & 16) ? 8 : 0;                           // k half
  const int b_row = wn + (lane & 7) + ((lane & 16) ? 8 : 0);       // + pair*16
  const int b_sel = (lane & 8) ? 8 : 0;                            // k half

  const uint32_t uAh = smem_u32(sAh), uAl = smem_u32(sAl);
  const uint32_t uWh = smem_u32(sWh), uWl = smem_u32(sWl);

  float c[2][4][4];
#pragma unroll
  for (int mt = 0; mt < 2; ++mt)
#pragma unroll
    for (int nt = 0; nt < 4; ++nt)
#pragma unroll
      for (int r = 0; r < 4; ++r) c[mt][nt][r] = 0.0f;

  for (int ch = 0; ch < H_DIM / 64; ++ch) {
    const int k0 = ch * 64;
    {  // A tiles: 2 threads/row, 32 bf16 = 64 B = 4 x uint4 each
      int r = tid >> 1, h = (tid & 1) * 32;
      const uint4* srch = reinterpret_cast<const uint4*>(g_ah + (size_t)(bm + r) * H_DIM + k0 + h);
      const uint4* srcl = reinterpret_cast<const uint4*>(g_al + (size_t)(bm + r) * H_DIM + k0 + h);
      uint4* dh = reinterpret_cast<uint4*>(sAh + r * MS_STRIDE + h);
      uint4* dl = reinterpret_cast<uint4*>(sAl + r * MS_STRIDE + h);
#pragma unroll
      for (int i = 0; i < 4; ++i) { dh[i] = srch[i]; dl[i] = srcl[i]; }
    }
    if (tid < 128) {  // W tiles: 64 rows
      int r = tid >> 1, h = (tid & 1) * 32;
      const uint4* srch = reinterpret_cast<const uint4*>(g_wh + (size_t)(bn + r) * H_DIM + k0 + h);
      const uint4* srcl = reinterpret_cast<const uint4*>(g_wl + (size_t)(bn + r) * H_DIM + k0 + h);
      uint4* dh = reinterpret_cast<uint4*>(sWh + r * MS_STRIDE + h);
      uint4* dl = reinterpret_cast<uint4*>(sWl + r * MS_STRIDE + h);
#pragma unroll
      for (int i = 0; i < 4; ++i) { dh[i] = srch[i]; dl[i] = srcl[i]; }
    }
    __syncthreads();

#pragma unroll
    for (int ks = 0; ks < 4; ++ks) {
      const int ak = ks * 16 + a_sel;
      const int bk = ks * 16 + b_sel;
      uint32_t ah[2][4], al[2][4], bh[4][2], bl[4][2];

      // A fragments: one x4 per (mt, h/l)
      uint32_t aoff0 = (uint32_t)(a_row * MS_STRIDE + ak) * 2;
      uint32_t aoff1 = aoff0 + 16 * MS_STRIDE * 2;
      LDMX4(ah[0][0], ah[0][1], ah[0][2], ah[0][3], uAh + aoff0);
      LDMX4(ah[1][0], ah[1][1], ah[1][2], ah[1][3], uAh + aoff1);
      LDMX4(al[0][0], al[0][1], al[0][2], al[0][3], uAl + aoff0);
      LDMX4(al[1][0], al[1][1], al[1][2], al[1][3], uAl + aoff1);

      // B fragments: one x4 per (nt-pair, h/l); regs = b0(nt),b1(nt),b0(nt+1),b1(nt+1)
      uint32_t boff0 = (uint32_t)(b_row * MS_STRIDE + bk) * 2;
      uint32_t boff1 = boff0 + 16 * MS_STRIDE * 2;
      LDMX4(bh[0][0], bh[0][1], bh[1][0], bh[1][1], uWh + boff0);
      LDMX4(bh[2][0], bh[2][1], bh[3][0], bh[3][1], uWh + boff1);
      LDMX4(bl[0][0], bl[0][1], bl[1][0], bl[1][1], uWl + boff0);
      LDMX4(bl[2][0], bl[2][1], bl[3][0], bl[3][1], uWl + boff1);

#pragma unroll
      for (int mt = 0; mt < 2; ++mt)
#pragma unroll
        for (int nt = 0; nt < 4; ++nt) {
          mma_bf16(c[mt][nt], ah[mt][0], ah[mt][1], ah[mt][2], ah[mt][3],
                   bh[nt][0], bh[nt][1]);
          mma_bf16(c[mt][nt], ah[mt][0], ah[mt][1], ah[mt][2], ah[mt][3],
                   bl[nt][0], bl[nt][1]);
          mma_bf16(c[mt][nt], al[mt][0], al[mt][1], al[mt][2], al[mt][3],
                   bh[nt][0], bh[nt][1]);
        }
    }
    __syncthreads();
  }

#pragma unroll
  for (int mt = 0; mt < 2; ++mt) {
#pragma unroll
    for (int nt = 0; nt < 4; ++nt) {
      int row = bm + wm + mt * 16 + g;
      int col = bn + wn + nt * 8 + q * 2;
      float2* p0 = reinterpret_cast<float2*>(g_ms + (size_t)row * MSPAD + col);
      float2* p1 = reinterpret_cast<float2*>(g_ms + (size_t)(row + 8) * MSPAD + col);
      *p0 = make_float2(c[mt][nt][0], c[mt][nt][1]);
      *p1 = make_float2(c[mt][nt][2], c[mt][nt][3]);
    }
  }
}

// ---------------- Sampling: one warp per (s,b) row ----------------
__global__ void __launch_bounds__(256) sample_kernel(const float* __restrict__ bias,
                                                     float* __restrict__ out) {
  int gw = (int)((blockIdx.x * blockDim.x + threadIdx.x) >> 5);
  int lane = (int)(threadIdx.x & 31);
  if (gw >= SB) return;
  const float* rmix = g_mix + (size_t)gw * MIXCH;

  float v = __int_as_float(0xFF800000);
  int vi = lane;
  if (lane < 4)
    v = __fadd_rn(__fdiv_rn(rmix[lane], 1e-4f),
                  gumbel_at(KCMD0, KCMD1, (unsigned)(gw * 4 + lane)));
#pragma unroll
  for (int off = 16; off > 0; off >>= 1) {
    float vo = __shfl_xor_sync(FULLMASK, v, off);
    int io = __shfl_xor_sync(FULLMASK, vi, off);
    if (vo > v || (vo == v && io < vi)) { v = vo; vi = io; }
  }
  if (lane < 4) out[(size_t)gw * 10 + lane] = (lane == vi) ? 1.0f : 0.0f;

  for (int j = 0; j < 6; ++j) {
    const float* p = rmix + 4 + j * 50;
    const int t1 = lane + 32;
    const bool has1 = (t1 < NMIX);
    float x0 = p[lane];
    float x1 = has1 ? p[t1] : __int_as_float(0xFF800000);

    float mx = fmaxf(x0, x1);
#pragma unroll
    for (int off = 16; off > 0; off >>= 1)
      mx = fmaxf(mx, __shfl_xor_sync(FULLMASK, mx, off));
    float s = expf(x0 - mx) + (has1 ? expf(x1 - mx) : 0.0f);
#pragma unroll
    for (int off = 16; off > 0; off >>= 1)
      s += __shfl_xor_sync(FULLMASK, s, off);
    float lse = logf(s) + mx;

    float y0 = __fdiv_rn(__fadd_rn(x0, -lse), 1e-4f);
    float y1 = has1 ? __fdiv_rn(__fadd_rn(x1, -lse), 1e-4f) : __int_as_float(0xFF800000);
    float ym = fmaxf(y0, y1);
#pragma unroll
    for (int off = 16; off > 0; off >>= 1)
      ym = fmaxf(ym, __shfl_xor_sync(FULLMASK, ym, off));

    float thr = ym - 20.45f;  // gumbel spread <= 20.412
    unsigned m0 = __ballot_sync(FULLMASK, y0 >= thr);
    unsigned m1 = __ballot_sync(FULLMASK, has1 && (y1 >= thr));
    int mixidx;
    if (__popc(m0) + __popc(m1) == 1) {
      mixidx = m0 ? (__ffs(m0) - 1) : (__ffs(m1) + 31);
    } else {
      unsigned base = (unsigned)(gw * 6 + j) * 50u;
      float z = __int_as_float(0xFF800000);
      int zi = 64;
      if (y0 >= thr) { z = __fadd_rn(y0, gumbel_at(KMIX0, KMIX1, base + (unsigned)lane)); zi = lane; }
      if (has1 && y1 >= thr) {
        float z1 = __fadd_rn(y1, gumbel_at(KMIX0, KMIX1, base + (unsigned)t1));
        if (z1 > z) { z = z1; zi = t1; }
      }
#pragma unroll
      for (int off = 16; off > 0; off >>= 1) {
        float zo = __shfl_xor_sync(FULLMASK, z, off);
        int io = __shfl_xor_sync(FULLMASK, zi, off);
        if (zo > z || (zo == z && io < zi)) { z = zo; zi = io; }
      }
      mixidx = zi;
    }

    if (lane == 0) {
      const float* rms = g_ms + (size_t)gw * MSPAD + j * 100;
      float mean = __fadd_rn(rms[mixidx], __ldg(&bias[4 + 150 * j + 50 + mixidx]));
      float lstd = __fadd_rn(rms[50 + mixidx], __ldg(&bias[4 + 150 * j + 100 + mixidx]));
      float nrm = normal_at(KG0, KG1, (unsigned)(gw * 6 + j));
      float noise = __fmul_rn(nrm, 0.01f);
      out[(size_t)gw * 10 + 4 + j] = __fadd_rn(mean, __fmul_rn(expf(lstd), noise));
    }
  }
}

// ---------------- Launch: fork ms-path onto a second stream ----------------
extern "C" void kernel_launch(void* const* d_in, const int* in_sizes, int n_in,
                              void* d_out, int out_size) {
  const float* A = (const float*)d_in[0];
  const float* W = (const float*)d_in[1];
  const float* bias = (const float*)d_in[2];
  float* out = (float*)d_out;

  static cudaStream_t s2 = nullptr;
  static cudaEvent_t ev_a = nullptr, ev_ms = nullptr;
  if (s2 == nullptr) {
    cudaStreamCreateWithFlags(&s2, cudaStreamNonBlocking);
    cudaEventCreateWithFlags(&ev_a, cudaEventDisableTiming);
    cudaEventCreateWithFlags(&ev_ms, cudaEventDisableTiming);
  }

  const int ms_smem = (128 + 128 + 64 + 64) * MS_STRIDE * 2;  // 55296 B
  static bool attr_set = false;
  if (!attr_set) {
    cudaFuncSetAttribute(gemm_ms_kernel,
                         cudaFuncAttributeMaxDynamicSharedMemorySize, ms_smem);
    attr_set = true;
  }

  // stream 0: split_a -> (fork) -> gemm_mix -> (join) -> sample
  split_a_kernel<<<(int)((size_t)SB * H_DIM / 4 / 256), 256>>>(A);
  cudaEventRecord(ev_a, 0);
  cudaStreamWaitEvent(s2, ev_a, 0);

  // stream s2: split_w -> gemm_ms (tensor pipe; concurrent with FFMA mix GEMM)
  split_w_kernel<<<(int)((size_t)MSPAD * H_DIM / 4 / 256), 256, 0, s2>>>(W);
  dim3 gms(MSPAD / 64, SB / 128);  // (10, 816)
  gemm_ms_kernel<<<gms, 256, ms_smem, s2>>>();
  cudaEventRecord(ev_ms, s2);

  dim3 gmix(MIXCH / BN + (MIXCH % BN != 0), SB / BM);  // (5, 816)
  gemm_mix_kernel<<<gmix, 128>>>(A, W, bias);

  cudaStreamWaitEvent(0, ev_ms, 0);
  sample_kernel<<<SB / 8, 256>>>(bias, out);
}

// round 13
// speedup vs baseline: 1.9167x; 1.3333x over previous
#include <cuda_runtime.h>
#include <cuda_bf16.h>
#include <math.h>
#include <stdint.h>

#define H_DIM 1024
#define SB 104448
#define OUT_CH 904
#define NMIX 50
#define NPAD 960            // 904 channels padded to 960 (15 x 64)
#define FULLMASK 0xFFFFFFFFu
#define MARGIN_THR 0.75f    // decision-safe margin (>= 2x worst-case y error)
#define WIN_BASE 20.45f     // exact gumbel-window (spread <= 20.412)
#define WIN_WIDE 21.25f     // widened window for approx candidate capture
#define FLAG_CAP (1 << 20)  // >= SB*7 max possible flags
typedef unsigned long long ull;

__device__ __forceinline__ float fadd_s(float a, float b) { return __fadd_rn(a, b); }

// ---------------- Threefry2x32 (JAX partitionable) ----------------
struct U2 { unsigned a, b; };
__host__ __device__ constexpr unsigned rotl32(unsigned x, int r) {
  return (x << r) | (x >> (32 - r));
}
__host__ __device__ constexpr U2 threefry2x32(unsigned k0, unsigned k1,
                                              unsigned c0, unsigned c1) {
  unsigned ks[3] = {k0, k1, k0 ^ k1 ^ 0x1BD11BDAu};
  unsigned x0 = c0 + k0, x1 = c1 + k1;
  const int rot[2][4] = {{13, 15, 26, 6}, {17, 29, 16, 24}};
#pragma unroll
  for (int g = 0; g < 5; ++g) {
    const int* r = rot[g & 1];
#pragma unroll
    for (int i = 0; i < 4; ++i) { x0 += x1; x1 = rotl32(x1, r[i]); x1 ^= x0; }
    x0 += ks[(g + 1) % 3];
    x1 += ks[(g + 2) % 3] + (unsigned)(g + 1);
  }
  return U2{x0, x1};
}
constexpr unsigned KCMD0 = threefry2x32(0u, 42u, 0u, 0u).a;
constexpr unsigned KCMD1 = threefry2x32(0u, 42u, 0u, 0u).b;
constexpr unsigned KMIX0 = threefry2x32(0u, 42u, 0u, 1u).a;
constexpr unsigned KMIX1 = threefry2x32(0u, 42u, 0u, 1u).b;
constexpr unsigned KG0   = threefry2x32(0u, 42u, 0u, 2u).a;
constexpr unsigned KG1   = threefry2x32(0u, 42u, 0u, 2u).b;

__device__ __forceinline__ float bits_to_f01(unsigned k0, unsigned k1, unsigned idx) {
  U2 o = threefry2x32(k0, k1, 0u, idx);
  return __uint_as_float((((o.a ^ o.b) >> 9) | 0x3f800000u)) - 1.0f;
}
__device__ __forceinline__ float gumbel_at(unsigned k0, unsigned k1, unsigned idx) {
  float u = fmaxf(bits_to_f01(k0, k1, idx), 1.17549435e-38f);
  return -logf(-logf(u));
}
__device__ __forceinline__ float normal_at(unsigned k0, unsigned k1, unsigned idx) {
  const float lo = __int_as_float(0xBF7FFFFF);  // nextafterf(-1,0)
  float u = fmaxf(__fadd_rn(__fmul_rn(bits_to_f01(k0, k1, idx), 2.0f), lo), lo);
  return __fmul_rn(1.41421356237f, erfinvf(u));
}

// ---------------- Device scratch ----------------
__device__ float g_full[(size_t)SB * NPAD];          // all 904 logits + bias (HMMA)
__device__ __nv_bfloat16 g_ah[(size_t)SB * H_DIM];
__device__ __nv_bfloat16 g_al[(size_t)SB * H_DIM];
__device__ __nv_bfloat16 g_wh[(size_t)NPAD * H_DIM];
__device__ __nv_bfloat16 g_wl[(size_t)NPAD * H_DIM];
__device__ int g_cnt;
__device__ int g_list[FLAG_CAP];

__global__ void zero_cnt_kernel() { g_cnt = 0; }

// ---------------- Splitters ----------------
__global__ void __launch_bounds__(256) split_a_kernel(const float* __restrict__ A) {
  size_t i = (size_t)blockIdx.x * 256 + threadIdx.x;
  float4 v = reinterpret_cast<const float4*>(A)[i];
  float f[4] = {v.x, v.y, v.z, v.w};
  ull hp = 0, lp = 0;
#pragma unroll
  for (int j = 0; j < 4; ++j) {
    __nv_bfloat16 h = __float2bfloat16(f[j]);
    __nv_bfloat16 l = __float2bfloat16(__fadd_rn(f[j], -__bfloat162float(h)));
    hp |= (ull)__bfloat16_as_ushort(h) << (16 * j);
    lp |= (ull)__bfloat16_as_ushort(l) << (16 * j);
  }
  reinterpret_cast<ull*>(g_ah)[i] = hp;
  reinterpret_cast<ull*>(g_al)[i] = lp;
}

__global__ void __launch_bounds__(256) split_w_kernel(const float* __restrict__ W) {
  size_t i = (size_t)blockIdx.x * 256 + threadIdx.x;  // one float4-slot
  int n = (int)(i / (H_DIM / 4));
  int k4 = (int)(i % (H_DIM / 4));
  ull hp = 0, lp = 0;
  if (n < OUT_CH) {
    float4 v = reinterpret_cast<const float4*>(W + (size_t)n * H_DIM)[k4];
    float f[4] = {v.x, v.y, v.z, v.w};
#pragma unroll
    for (int j = 0; j < 4; ++j) {
      __nv_bfloat16 h = __float2bfloat16(f[j]);
      __nv_bfloat16 l = __float2bfloat16(__fadd_rn(f[j], -__bfloat162float(h)));
      hp |= (ull)__bfloat16_as_ushort(h) << (16 * j);
      lp |= (ull)__bfloat16_as_ushort(l) << (16 * j);
    }
  }
  reinterpret_cast<ull*>(g_wh)[i] = hp;
  reinterpret_cast<ull*>(g_wl)[i] = lp;
}

// ---------------- HMMA GEMM (mma.sync bf16 + ldmatrix): ALL 904 channels -----
// D = Ah*Wh + Ah*Wl + Al*Wh (+bias). Block 128x64, 8 warps (4m x 2n).
#define MS_STRIDE 72  // 64 + 8 pad; 144B = 9*16B rows -> conflict-free ldmatrix

__device__ __forceinline__ void mma_bf16(float c[4], uint32_t a0, uint32_t a1,
                                         uint32_t a2, uint32_t a3,
                                         uint32_t b0, uint32_t b1) {
  asm volatile(
      "mma.sync.aligned.m16n8k16.row.col.f32.bf16.bf16.f32 "
      "{%0,%1,%2,%3}, {%4,%5,%6,%7}, {%8,%9}, {%0,%1,%2,%3};"
      : "+f"(c[0]), "+f"(c[1]), "+f"(c[2]), "+f"(c[3])
      : "r"(a0), "r"(a1), "r"(a2), "r"(a3), "r"(b0), "r"(b1));
}

#define LDMX4(R0, R1, R2, R3, ADDR)                                            \
  asm volatile("ldmatrix.sync.aligned.m8n8.x4.shared.b16 {%0,%1,%2,%3}, [%4];" \
               : "=r"(R0), "=r"(R1), "=r"(R2), "=r"(R3) : "r"(ADDR))

__device__ __forceinline__ uint32_t smem_u32(const void* p) {
  uint32_t a;
  asm("{ .reg .u64 t; cvta.to.shared.u64 t, %1; cvt.u32.u64 %0, t; }" : "=r"(a) : "l"(p));
  return a;
}

__global__ void __launch_bounds__(256) gemm_full_kernel(const float* __restrict__ bias) {
  extern __shared__ __nv_bfloat16 sm[];
  __nv_bfloat16* sAh = sm;
  __nv_bfloat16* sAl = sAh + 128 * MS_STRIDE;
  __nv_bfloat16* sWh = sAl + 128 * MS_STRIDE;
  __nv_bfloat16* sWl = sWh + 64 * MS_STRIDE;

  const int bn = blockIdx.x * 64;   // 15 (fastest -> A hot in L2)
  const int bm = blockIdx.y * 128;  // 816
  const int tid = (int)threadIdx.x;
  const int wid = tid >> 5, lane = tid & 31;
  const int wm = (wid >> 1) * 32, wn = (wid & 1) * 32;
  const int g = lane >> 2, q = lane & 3;

  const int a_row = wm + (lane & 15);
  const int a_sel = (lane & 16) ? 8 : 0;
  const int b_row = wn + (lane & 7) + ((lane & 16) ? 8 : 0);
  const int b_sel = (lane & 8) ? 8 : 0;

  const uint32_t uAh = smem_u32(sAh), uAl = smem_u32(sAl);
  const uint32_t uWh = smem_u32(sWh), uWl = smem_u32(sWl);

  float c[2][4][4];
#pragma unroll
  for (int mt = 0; mt < 2; ++mt)
#pragma unroll
    for (int nt = 0; nt < 4; ++nt)
#pragma unroll
      for (int r = 0; r < 4; ++r) c[mt][nt][r] = 0.0f;

  for (int ch = 0; ch < H_DIM / 64; ++ch) {
    const int k0 = ch * 64;
    {  // A tiles: 2 threads/row, 32 bf16 = 64 B = 4 x uint4 each
      int r = tid >> 1, h = (tid & 1) * 32;
      const uint4* srch = reinterpret_cast<const uint4*>(g_ah + (size_t)(bm + r) * H_DIM + k0 + h);
      const uint4* srcl = reinterpret_cast<const uint4*>(g_al + (size_t)(bm + r) * H_DIM + k0 + h);
      uint4* dh = reinterpret_cast<uint4*>(sAh + r * MS_STRIDE + h);
      uint4* dl = reinterpret_cast<uint4*>(sAl + r * MS_STRIDE + h);
#pragma unroll
      for (int i = 0; i < 4; ++i) { dh[i] = srch[i]; dl[i] = srcl[i]; }
    }
    if (tid < 128) {  // W tiles: 64 rows
      int r = tid >> 1, h = (tid & 1) * 32;
      const uint4* srch = reinterpret_cast<const uint4*>(g_wh + (size_t)(bn + r) * H_DIM + k0 + h);
      const uint4* srcl = reinterpret_cast<const uint4*>(g_wl + (size_t)(bn + r) * H_DIM + k0 + h);
      uint4* dh = reinterpret_cast<uint4*>(sWh + r * MS_STRIDE + h);
      uint4* dl = reinterpret_cast<uint4*>(sWl + r * MS_STRIDE + h);
#pragma unroll
      for (int i = 0; i < 4; ++i) { dh[i] = srch[i]; dl[i] = srcl[i]; }
    }
    __syncthreads();

#pragma unroll
    for (int ks = 0; ks < 4; ++ks) {
      const int ak = ks * 16 + a_sel;
      const int bk = ks * 16 + b_sel;
      uint32_t ah[2][4], al[2][4], bh[4][2], bl[4][2];

      uint32_t aoff0 = (uint32_t)(a_row * MS_STRIDE + ak) * 2;
      uint32_t aoff1 = aoff0 + 16 * MS_STRIDE * 2;
      LDMX4(ah[0][0], ah[0][1], ah[0][2], ah[0][3], uAh + aoff0);
      LDMX4(ah[1][0], ah[1][1], ah[1][2], ah[1][3], uAh + aoff1);
      LDMX4(al[0][0], al[0][1], al[0][2], al[0][3], uAl + aoff0);
      LDMX4(al[1][0], al[1][1], al[1][2], al[1][3], uAl + aoff1);

      uint32_t boff0 = (uint32_t)(b_row * MS_STRIDE + bk) * 2;
      uint32_t boff1 = boff0 + 16 * MS_STRIDE * 2;
      LDMX4(bh[0][0], bh[0][1], bh[1][0], bh[1][1], uWh + boff0);
      LDMX4(bh[2][0], bh[2][1], bh[3][0], bh[3][1], uWh + boff1);
      LDMX4(bl[0][0], bl[0][1], bl[1][0], bl[1][1], uWl + boff0);
      LDMX4(bl[2][0], bl[2][1], bl[3][0], bl[3][1], uWl + boff1);

#pragma unroll
      for (int mt = 0; mt < 2; ++mt)
#pragma unroll
        for (int nt = 0; nt < 4; ++nt) {
          mma_bf16(c[mt][nt], ah[mt][0], ah[mt][1], ah[mt][2], ah[mt][3],
                   bh[nt][0], bh[nt][1]);
          mma_bf16(c[mt][nt], ah[mt][0], ah[mt][1], ah[mt][2], ah[mt][3],
                   bl[nt][0], bl[nt][1]);
          mma_bf16(c[mt][nt], al[mt][0], al[mt][1], al[mt][2], al[mt][3],
                   bh[nt][0], bh[nt][1]);
        }
    }
    __syncthreads();
  }

  // epilogue: +bias, store (skip padded cols >= 904)
#pragma unroll
  for (int mt = 0; mt < 2; ++mt) {
#pragma unroll
    for (int nt = 0; nt < 4; ++nt) {
      int row = bm + wm + mt * 16 + g;
      int col = bn + wn + nt * 8 + q * 2;
      if (col < OUT_CH) {
        float b0 = __ldg(&bias[col]), b1 = __ldg(&bias[col + 1]);
        float2* p0 = reinterpret_cast<float2*>(g_full + (size_t)row * NPAD + col);
        float2* p1 = reinterpret_cast<float2*>(g_full + (size_t)(row + 8) * NPAD + col);
        *p0 = make_float2(fadd_s(c[mt][nt][0], b0), fadd_s(c[mt][nt][1], b1));
        *p1 = make_float2(fadd_s(c[mt][nt][2], b0), fadd_s(c[mt][nt][3], b1));
      }
    }
  }
}

// ---------------- Sampling with safe-margin flagging ----------------
__global__ void __launch_bounds__(256) sample_kernel(float* __restrict__ out) {
  int gw = (int)((blockIdx.x * blockDim.x + threadIdx.x) >> 5);
  int lane = (int)(threadIdx.x & 31);
  if (gw >= SB) return;
  const float* row = g_full + (size_t)gw * NPAD;

  // ---- command: top-2 of (x/tau + gumbel) ----
  float m1 = __int_as_float(0xFF800000), m2 = m1;
  int i1 = lane;
  if (lane < 4)
    m1 = __fadd_rn(__fdiv_rn(row[lane], 1e-4f),
                   gumbel_at(KCMD0, KCMD1, (unsigned)(gw * 4 + lane)));
#pragma unroll
  for (int off = 16; off > 0; off >>= 1) {
    float om1 = __shfl_xor_sync(FULLMASK, m1, off);
    int oi1 = __shfl_xor_sync(FULLMASK, i1, off);
    float om2 = __shfl_xor_sync(FULLMASK, m2, off);
    if (om1 > m1 || (om1 == m1 && oi1 < i1)) {
      m2 = fmaxf(m1, om2); m1 = om1; i1 = oi1;
    } else {
      m2 = fmaxf(m2, om1);
    }
  }
  if (lane < 4) out[(size_t)gw * 10 + lane] = (lane == i1) ? 1.0f : 0.0f;
  if (lane == 0 && (m1 - m2) < MARGIN_THR) {
    int pos = atomicAdd(&g_cnt, 1);
    if (pos < FLAG_CAP) g_list[pos] = gw * 8 + 7;  // cmd row
  }

  // ---- 6 mixture rows ----
  for (int j = 0; j < 6; ++j) {
    const float* p = row + 4 + j * 150;
    const int t1 = lane + 32;
    const bool has1 = (t1 < NMIX);
    float x0 = p[lane];
    float x1 = has1 ? p[t1] : __int_as_float(0xFF800000);

    float mx = fmaxf(x0, x1);
#pragma unroll
    for (int off = 16; off > 0; off >>= 1)
      mx = fmaxf(mx, __shfl_xor_sync(FULLMASK, mx, off));
    float s = expf(x0 - mx) + (has1 ? expf(x1 - mx) : 0.0f);
#pragma unroll
    for (int off = 16; off > 0; off >>= 1)
      s += __shfl_xor_sync(FULLMASK, s, off);
    float lse = logf(s) + mx;

    float y0 = __fdiv_rn(__fadd_rn(x0, -lse), 1e-4f);
    float y1 = has1 ? __fdiv_rn(__fadd_rn(x1, -lse), 1e-4f) : __int_as_float(0xFF800000);
    float ym = fmaxf(y0, y1);
#pragma unroll
    for (int off = 16; off > 0; off >>= 1)
      ym = fmaxf(ym, __shfl_xor_sync(FULLMASK, ym, off));

    // widened window captures every possible exact candidate
    float thr = ym - WIN_WIDE;
    bool c0 = y0 >= thr;
    bool c1 = has1 && (y1 >= thr);
    unsigned b0m = __ballot_sync(FULLMASK, c0);
    unsigned b1m = __ballot_sync(FULLMASK, c1);
    int mixidx;
    if (__popc(b0m) + __popc(b1m) == 1) {
      mixidx = b0m ? (__ffs(b0m) - 1) : (__ffs(b1m) + 31);
    } else {
      unsigned base = (unsigned)(gw * 6 + j) * 50u;
      float z0 = c0 ? __fadd_rn(y0, gumbel_at(KMIX0, KMIX1, base + (unsigned)lane))
                    : __int_as_float(0xFF800000);
      float z1 = c1 ? __fadd_rn(y1, gumbel_at(KMIX0, KMIX1, base + (unsigned)t1))
                    : __int_as_float(0xFF800000);
      float w1 = z0, w2 = z1;
      int wi = lane;
      if (z1 > z0) { w1 = z1; wi = t1; w2 = z0; }
#pragma unroll
      for (int off = 16; off > 0; off >>= 1) {
        float ow1 = __shfl_xor_sync(FULLMASK, w1, off);
        int owi = __shfl_xor_sync(FULLMASK, wi, off);
        float ow2 = __shfl_xor_sync(FULLMASK, w2, off);
        if (ow1 > w1 || (ow1 == w1 && owi < wi)) {
          w2 = fmaxf(w1, ow2); w1 = ow1; wi = owi;
        } else {
          w2 = fmaxf(w2, ow1);
        }
      }
      mixidx = wi;
      if (lane == 0 && (w1 - w2) < MARGIN_THR) {
        int pos = atomicAdd(&g_cnt, 1);
        if (pos < FLAG_CAP) g_list[pos] = gw * 8 + j;
      }
    }

    if (lane == 0) {
      float mean = p[50 + mixidx];
      float lstd = p[100 + mixidx];
      float nrm = normal_at(KG0, KG1, (unsigned)(gw * 6 + j));
      float noise = __fmul_rn(nrm, 0.01f);
      out[(size_t)gw * 10 + 4 + j] = __fadd_rn(mean, __fmul_rn(expf(lstd), noise));
    }
  }
}

// ---------------- Fixup: exact kc=320 recompute for flagged rows -------------
__global__ void __launch_bounds__(64) fixup_kernel(
    const float* __restrict__ A, const float* __restrict__ W,
    const float* __restrict__ bias, float* __restrict__ out) {
  __shared__ float a_sm[H_DIM];
  __shared__ float x_sm[64];
  __shared__ float z_sm[64];

  int cnt = g_cnt;
  if (cnt > FLAG_CAP) cnt = FLAG_CAP;
  const int tid = (int)threadIdx.x;

  for (int it = (int)blockIdx.x; it < cnt; it += (int)gridDim.x) {
    int code = g_list[it];
    int gw = code >> 3, j = code & 7;

    // stage A row
    for (int k = tid; k < H_DIM; k += 64) a_sm[k] = A[(size_t)gw * H_DIM + k];
    __syncthreads();

    int nch = (j == 7) ? 4 : NMIX;
    int ch0 = (j == 7) ? 0 : 4 + 150 * j;

    float x = __int_as_float(0xFF800000);
    if (tid < nch) {
      const float* wr = W + (size_t)(ch0 + tid) * H_DIM;
      float acc = 0.0f, tot = 0.0f;
      int k = 0;
#pragma unroll 1
      for (int seg = 0; seg < 4; ++seg) {
        int ke = (seg < 3) ? (seg + 1) * 320 : H_DIM;
#pragma unroll 4
        for (; k < ke; ++k) acc = fmaf(a_sm[k], __ldg(&wr[k]), acc);
        tot = __fadd_rn(tot, acc);
        acc = 0.0f;
      }
      x = __fadd_rn(tot, __ldg(&bias[ch0 + tid]));
    }
    x_sm[tid] = x;
    __syncthreads();

    if (j == 7) {  // command row: argmax(x/tau + gumbel) over 4, exact
      if (tid == 0) {
        float best = __int_as_float(0xFF800000);
        int bi = 0;
        for (int c = 0; c < 4; ++c) {
          float v = __fadd_rn(__fdiv_rn(x_sm[c], 1e-4f),
                              gumbel_at(KCMD0, KCMD1, (unsigned)(gw * 4 + c)));
          if (v > best) { best = v; bi = c; }
        }
        for (int c = 0; c < 4; ++c)
          out[(size_t)gw * 10 + c] = (c == bi) ? 1.0f : 0.0f;
      }
    } else {  // mixture row: exact lse, window 20.45, gumbel-argmax
      if (tid == 0) {
        float mx = x_sm[0];
        for (int c = 1; c < NMIX; ++c) mx = fmaxf(mx, x_sm[c]);
        float s = 0.0f;
        for (int c = 0; c < NMIX; ++c) s = __fadd_rn(s, expf(x_sm[c] - mx));
        z_sm[0] = logf(s) + mx;
      }
      __syncthreads();
      float lse = z_sm[0];
      __syncthreads();
      float y = (tid < NMIX) ? __fdiv_rn(__fadd_rn(x_sm[tid], -lse), 1e-4f)
                             : __int_as_float(0xFF800000);
      x_sm[tid] = y;
      __syncthreads();
      if (tid == 0) {
        float ym = x_sm[0];
        for (int c = 1; c < NMIX; ++c) ym = fmaxf(ym, x_sm[c]);
        z_sm[1] = ym;
      }
      __syncthreads();
      float thr = z_sm[1] - WIN_BASE;
      unsigned base = (unsigned)(gw * 6 + j) * 50u;
      float z = __int_as_float(0xFF800000);
      if (tid < NMIX && y >= thr)
        z = __fadd_rn(y, gumbel_at(KMIX0, KMIX1, base + (unsigned)tid));
      z_sm[tid] = z;
      __syncthreads();
      if (tid == 0) {
        float best = __int_as_float(0xFF800000);
        int bi = 0;
        for (int c = 0; c < NMIX; ++c)
          if (z_sm[c] > best) { best = z_sm[c]; bi = c; }  // tie keeps lower
        const float* p = g_full + (size_t)gw * NPAD + 4 + 150 * j;
        float mean = p[50 + bi];
        float lstd = p[100 + bi];
        float nrm = normal_at(KG0, KG1, (unsigned)(gw * 6 + j));
        float noise = __fmul_rn(nrm, 0.01f);
        out[(size_t)gw * 10 + 4 + j] = __fadd_rn(mean, __fmul_rn(expf(lstd), noise));
      }
    }
    __syncthreads();
  }
}

// ---------------- Launch ----------------
extern "C" void kernel_launch(void* const* d_in, const int* in_sizes, int n_in,
                              void* d_out, int out_size) {
  const float* A = (const float*)d_in[0];
  const float* W = (const float*)d_in[1];
  const float* bias = (const float*)d_in[2];
  float* out = (float*)d_out;

  const int ms_smem = (128 + 128 + 64 + 64) * MS_STRIDE * 2;  // 55296 B
  static bool attr_set = false;
  if (!attr_set) {
    cudaFuncSetAttribute(gemm_full_kernel,
                         cudaFuncAttributeMaxDynamicSharedMemorySize, ms_smem);
    attr_set = true;
  }

  zero_cnt_kernel<<<1, 1>>>();
  split_a_kernel<<<(int)((size_t)SB * H_DIM / 4 / 256), 256>>>(A);
  split_w_kernel<<<(int)((size_t)NPAD * H_DIM / 4 / 256), 256>>>(W);

  dim3 gfull(NPAD / 64, SB / 128);  // (15, 816)
  gemm_full_kernel<<<gfull, 256, ms_smem>>>(bias);

  sample_kernel<<<SB / 8, 256>>>(out);
  fixup_kernel<<<1024, 64>>>(A, W, bias, out);
}